// round 1
// baseline (speedup 1.0000x reference)
#include <cuda_runtime.h>
#include <math.h>

// Problem constants
#define B     8192
#define C     64
#define HW    64      // 8x8 pixels
#define NPIX  4096    // C*HW per image
#define NSEP  (B*C)   // 524288 gate values
#define K_IDX 104857  // int(0.2 * 524288)
#define NSM   148

// ---------------- scratch (device globals: allocation-free) ----------------
__device__ float    g_y1[(size_t)B * NPIX];   // conv1 output (gated), 128 MiB
__device__ float    g_y2[(size_t)B * NPIX];   // conv2 output (raw),   128 MiB
__device__ float    g_sep[NSEP];              // sigmoid gate values
__device__ float    g_stats[256];             // [0:64] sum1 [64:128] sq1 [128:192] sum2 [192:256] sq2
__device__ float    g_bnp[256];               // [0:64] scale1 [64:128] shift1 [128:192] scale2 [192:256] shift2
__device__ unsigned g_bins[2048];
__device__ unsigned g_prefix;
__device__ unsigned g_krem;
__device__ float    g_thr;

// ---------------- SE gate: GAP -> fc1 -> relu -> fc2 -> sigmoid ------------
__global__ void k_gate(const float* __restrict__ x,
                       const float* __restrict__ w1, const float* __restrict__ b1,
                       const float* __restrict__ w2, const float* __restrict__ b2) {
    __shared__ float pooled[4][64];
    __shared__ float hid[4][16];
    int t = threadIdx.x;
    int img = t >> 6, c = t & 63;
    int b = blockIdx.x * 4 + img;

    const float4* xv = (const float4*)(x + (size_t)b * NPIX + c * 64);
    float s = 0.f;
#pragma unroll
    for (int j = 0; j < 16; ++j) { float4 v = xv[j]; s += v.x + v.y + v.z + v.w; }
    pooled[img][c] = s * (1.f / 64.f);
    __syncthreads();

    if (c < 16) {
        float h = b1[c];
#pragma unroll
        for (int i = 0; i < 64; ++i) h += pooled[img][i] * w1[c * 64 + i];
        hid[img][c] = fmaxf(h, 0.f);
    }
    __syncthreads();

    float o = b2[c];
#pragma unroll
    for (int j = 0; j < 16; ++j) o += hid[img][j] * w2[c * 16 + j];
    g_sep[b * 64 + c] = 1.f / (1.f + expf(-o));
}

// ---------------- radix-select init ----------------------------------------
__global__ void k_init() {
    int t = threadIdx.x;
    for (int i = t; i < 2048; i += 256) g_bins[i] = 0;
    if (t < 256) g_stats[t] = 0.f;
    if (t == 0) { g_prefix = 0; g_krem = K_IDX; }
}

// histogram pass over positive-float keys (uint order == float order)
__global__ void k_hist(int pass) {
    __shared__ unsigned sb[2048];
    int t = threadIdx.x;
    for (int i = t; i < 2048; i += 256) sb[i] = 0;
    __syncthreads();
    unsigned pref = g_prefix;
    for (int i = blockIdx.x * 256 + t; i < NSEP; i += gridDim.x * 256) {
        unsigned key = __float_as_uint(g_sep[i]);
        if (pass == 0) {
            atomicAdd(&sb[key >> 21], 1u);
        } else if (pass == 1) {
            if ((key >> 21) == pref) atomicAdd(&sb[(key >> 10) & 2047u], 1u);
        } else {
            if ((key >> 10) == pref) atomicAdd(&sb[key & 1023u], 1u);
        }
    }
    __syncthreads();
    for (int i = t; i < 2048; i += 256) if (sb[i]) atomicAdd(&g_bins[i], sb[i]);
}

__global__ void k_scan(int pass) {
    if (threadIdx.x == 0) {
        unsigned k = g_krem, cum = 0;
        int sel = 0;
        int nb = (pass == 2) ? 1024 : 2048;
        for (int i = 0; i < nb; ++i) {
            unsigned cc = g_bins[i];
            if (cum + cc > k) { sel = i; break; }
            cum += cc;
        }
        g_krem = k - cum;
        unsigned p = (g_prefix << ((pass == 2) ? 10 : 11)) | (unsigned)sel;
        g_prefix = p;
        if (pass == 2) g_thr = __uint_as_float(p);
    }
    __syncthreads();
    for (int i = threadIdx.x; i < 2048; i += blockDim.x) g_bins[i] = 0;
}

// ---------------- direct 3x3 conv (fp32), persistent, fused pre/post -------
// STAGE 1: in = x, epilogue: *gate, bn1 stats, out = g_y1
// STAGE 2: in = relu(bn1(g_y1)) (fused at load), bn2 stats, out = g_y2
// SMEM: ws[36864] weights (i,k,o layout), xs[15360] padded tiles / out staging,
//       bnsum[64], bnsq[64], gsm[128]
template <int STAGE>
__global__ __launch_bounds__(256, 1)
void k_conv(const float* __restrict__ xin, const float* __restrict__ wq) {
    extern __shared__ float sm[];
    float* ws    = sm;              // 36864 floats
    float* xs    = ws + 36864;      // 15360 floats (2 imgs * 64ch * 120)
    float* bnsum = xs + 15360;      // 64
    float* bnsq  = bnsum + 64;      // 64
    float* gsm   = bnsq + 64;       // 128

    int t = threadIdx.x;

    // weights: global [o][i][ky][kx] -> smem [(i*9+k)*64 + o]
    for (int idx = t; idx < 36864; idx += 256) {
        int o = idx / 576, r = idx - o * 576;
        ws[r * 64 + o] = wq[idx];
    }
    if (t < 64) { bnsum[t] = 0.f; bnsq[t] = 0.f; }
    __syncthreads();

    int img = t >> 7;        // 0..1
    int rr  = t & 127;
    int oy  = rr >> 4;       // 0..7
    int og  = rr & 15;       // 0..15
    int o0  = og * 4;

    float thr = (STAGE == 1) ? g_thr : 0.f;
    const float4* wv4 = (const float4*)ws;
    float* yout = (STAGE == 1) ? g_y1 : g_y2;
    const float* src_base = (STAGE == 1) ? xin : (const float*)g_y1;

    for (int pair = blockIdx.x; pair < B / 2; pair += gridDim.x) {
        size_t base = (size_t)pair * 2 * NPIX;

        // zero padded tiles
        for (int i = t; i < 15360; i += 256) xs[i] = 0.f;
        if (STAGE == 1 && t < 128) {
            int ii = t >> 6, cc = t & 63;
            gsm[t] = fmaxf(g_sep[(pair * 2 + ii) * 64 + cc] - thr, 0.f);
        }
        __syncthreads();

        // load interior (+ fused relu(bn1) for STAGE 2)
        const float4* src = (const float4*)(src_base + base);
        for (int v = t; v < 2048; v += 256) {
            float4 d = src[v];
            int im  = v >> 10;
            int rem = v & 1023;
            int c   = rem >> 4;
            int q   = rem & 15;
            int y   = q >> 1;
            int x0  = (q & 1) * 4;
            float vv[4] = {d.x, d.y, d.z, d.w};
            float* dst = xs + im * 7680 + c * 120 + (y + 1) * 12 + x0 + 1;
            if (STAGE == 2) {
                float s1 = g_bnp[c], h1 = g_bnp[64 + c];
#pragma unroll
                for (int e = 0; e < 4; ++e) dst[e] = fmaxf(fmaf(vv[e], s1, h1), 0.f);
            } else {
#pragma unroll
                for (int e = 0; e < 4; ++e) dst[e] = vv[e];
            }
        }
        __syncthreads();

        // compute: 4 out-channels x 8 out-x for row oy
        float a[4][8];
#pragma unroll
        for (int j = 0; j < 4; ++j)
#pragma unroll
            for (int ox = 0; ox < 8; ++ox) a[j][ox] = 0.f;

        const float* xc = xs + img * 7680 + oy * 12;
#pragma unroll 2
        for (int i = 0; i < 64; ++i) {
            const float* xci = xc + i * 120;
#pragma unroll
            for (int ky = 0; ky < 3; ++ky) {
                const float* xr = xci + ky * 12;
                float4 p0 = *(const float4*)(xr);
                float4 p1 = *(const float4*)(xr + 4);
                float4 p2 = *(const float4*)(xr + 8);
                float xv[10] = {p0.x, p0.y, p0.z, p0.w,
                                p1.x, p1.y, p1.z, p1.w,
                                p2.x, p2.y};
#pragma unroll
                for (int kx = 0; kx < 3; ++kx) {
                    float4 w = wv4[(i * 9 + ky * 3 + kx) * 16 + og];
#pragma unroll
                    for (int ox = 0; ox < 8; ++ox) {
                        float xvv = xv[ox + kx];
                        a[0][ox] = fmaf(w.x, xvv, a[0][ox]);
                        a[1][ox] = fmaf(w.y, xvv, a[1][ox]);
                        a[2][ox] = fmaf(w.z, xvv, a[2][ox]);
                        a[3][ox] = fmaf(w.w, xvv, a[3][ox]);
                    }
                }
            }
        }
        __syncthreads();   // all xs reads done before reuse as out staging

        // epilogue: gate (STAGE1), bn stats, stage to smem (padded stride 65)
        float* os = xs;
#pragma unroll
        for (int j = 0; j < 4; ++j) {
            float g = (STAGE == 1) ? gsm[img * 64 + o0 + j] : 1.f;
            float ls = 0.f, lq = 0.f;
#pragma unroll
            for (int ox = 0; ox < 8; ++ox) {
                float v = a[j][ox] * g;
                ls += v;
                lq += v * v;
                os[img * 4160 + (o0 + j) * 65 + oy * 8 + ox] = v;
            }
            atomicAdd(&bnsum[o0 + j], ls);
            atomicAdd(&bnsq[o0 + j], lq);
        }
        __syncthreads();

        // coalesced global writeback
        for (int e = t; e < 8192; e += 256) {
            int im = e >> 12, r2 = e & 4095;
            int o = r2 >> 6, p = r2 & 63;
            yout[base + e] = os[im * 4160 + o * 65 + p];
        }
        __syncthreads();
    }

    // flush bn partial stats
    if (t < 64) {
        int off = (STAGE == 1) ? 0 : 128;
        atomicAdd(&g_stats[off + t], bnsum[t]);
        atomicAdd(&g_stats[off + 64 + t], bnsq[t]);
    }
}

// ---------------- BN finalize ----------------------------------------------
__global__ void k_bnfin(int stage, const float* __restrict__ gamma,
                        const float* __restrict__ beta) {
    int c = threadIdx.x;
    if (c >= 64) return;
    int off = (stage == 1) ? 0 : 128;
    float n = (float)NSEP;
    float mean = g_stats[off + c] / n;
    float var  = g_stats[off + 64 + c] / n - mean * mean;
    float inv  = rsqrtf(var + 1e-5f);
    float s    = gamma[c] * inv;
    g_bnp[off + c]      = s;
    g_bnp[off + 64 + c] = beta[c] - mean * s;
}

// ---------------- final: relu(bn2(y2) + x) ----------------------------------
__global__ void k_final(const float* __restrict__ x, float* __restrict__ out) {
    const float4* xv = (const float4*)x;
    const float4* yv = (const float4*)g_y2;
    float4* ov = (float4*)out;
    int total = (B * NPIX) / 4;
    for (int i = blockIdx.x * blockDim.x + threadIdx.x; i < total;
         i += gridDim.x * blockDim.x) {
        int c = (i >> 4) & 63;
        float s = g_bnp[128 + c], h = g_bnp[192 + c];
        float4 v = yv[i], r = xv[i], o;
        o.x = fmaxf(fmaf(v.x, s, h) + r.x, 0.f);
        o.y = fmaxf(fmaf(v.y, s, h) + r.y, 0.f);
        o.z = fmaxf(fmaf(v.z, s, h) + r.z, 0.f);
        o.w = fmaxf(fmaf(v.w, s, h) + r.w, 0.f);
        ov[i] = o;
    }
}

// ---------------- launch ----------------------------------------------------
extern "C" void kernel_launch(void* const* d_in, const int* in_sizes, int n_in,
                              void* d_out, int out_size) {
    const float* x   = (const float*)d_in[0];
    const float* c1w = (const float*)d_in[1];
    const float* c2w = (const float*)d_in[2];
    const float* f1w = (const float*)d_in[3];
    const float* f1b = (const float*)d_in[4];
    const float* f2w = (const float*)d_in[5];
    const float* f2b = (const float*)d_in[6];
    const float* g1  = (const float*)d_in[7];
    const float* b1  = (const float*)d_in[8];
    const float* g2  = (const float*)d_in[9];
    const float* b2  = (const float*)d_in[10];
    float* out = (float*)d_out;

    const int SMEM_BYTES = (36864 + 15360 + 64 + 64 + 128) * 4;  // 209920
    cudaFuncSetAttribute(k_conv<1>, cudaFuncAttributeMaxDynamicSharedMemorySize, SMEM_BYTES);
    cudaFuncSetAttribute(k_conv<2>, cudaFuncAttributeMaxDynamicSharedMemorySize, SMEM_BYTES);

    // 1) SE gate values
    k_gate<<<B / 4, 256>>>(x, f1w, f1b, f2w, f2b);

    // 2) exact 20%-quantile threshold via 3-pass radix select
    k_init<<<1, 256>>>();
    for (int p = 0; p < 3; ++p) {
        k_hist<<<256, 256>>>(p);
        k_scan<<<1, 256>>>(p);
    }

    // 3) conv1 * gate, bn1 stats
    k_conv<1><<<NSM, 256, SMEM_BYTES>>>(x, c1w);
    k_bnfin<<<1, 64>>>(1, g1, b1);

    // 4) conv2(relu(bn1(.))), bn2 stats
    k_conv<2><<<NSM, 256, SMEM_BYTES>>>(x, c2w);
    k_bnfin<<<1, 64>>>(2, g2, b2);

    // 5) relu(bn2 + residual)
    k_final<<<2048, 256>>>(x, out);
}

// round 2
// speedup vs baseline: 1.0019x; 1.0019x over previous
#include <cuda_runtime.h>
#include <math.h>

// Problem constants
#define B     8192
#define C     64
#define HW    64      // 8x8 pixels
#define NPIX  4096    // C*HW per image
#define NSEP  (B*C)   // 524288 gate values
#define K_IDX 104857  // int(0.2 * 524288)
#define NSM   148

// ---------------- scratch (device globals: allocation-free) ----------------
__device__ float    g_y1[(size_t)B * NPIX];   // conv1 output (gated), 128 MiB
__device__ float    g_y2[(size_t)B * NPIX];   // conv2 output (raw),   128 MiB
__device__ float    g_sep[NSEP];              // sigmoid gate values
__device__ float    g_stats[256];             // [0:64] sum1 [64:128] sq1 [128:192] sum2 [192:256] sq2
__device__ float    g_bnp[256];               // [0:64] scale1 [64:128] shift1 [128:192] scale2 [192:256] shift2
__device__ unsigned g_bins[2048];
__device__ unsigned g_prefix;
__device__ unsigned g_krem;
__device__ float    g_thr;

// ---------------- SE gate: GAP -> fc1 -> relu -> fc2 -> sigmoid ------------
__global__ void k_gate(const float* __restrict__ x,
                       const float* __restrict__ w1, const float* __restrict__ b1,
                       const float* __restrict__ w2, const float* __restrict__ b2) {
    __shared__ float pooled[4][64];
    __shared__ float hid[4][16];
    int t = threadIdx.x;
    int img = t >> 6, c = t & 63;
    int b = blockIdx.x * 4 + img;

    const float4* xv = (const float4*)(x + (size_t)b * NPIX + c * 64);
    float s = 0.f;
#pragma unroll
    for (int j = 0; j < 16; ++j) { float4 v = xv[j]; s += v.x + v.y + v.z + v.w; }
    pooled[img][c] = s * (1.f / 64.f);
    __syncthreads();

    if (c < 16) {
        float h = b1[c];
#pragma unroll
        for (int i = 0; i < 64; ++i) h += pooled[img][i] * w1[c * 64 + i];
        hid[img][c] = fmaxf(h, 0.f);
    }
    __syncthreads();

    float o = b2[c];
#pragma unroll
    for (int j = 0; j < 16; ++j) o += hid[img][j] * w2[c * 16 + j];
    g_sep[b * 64 + c] = 1.f / (1.f + expf(-o));
}

// ---------------- radix-select init ----------------------------------------
__global__ void k_init() {
    int t = threadIdx.x;
    for (int i = t; i < 2048; i += 256) g_bins[i] = 0;
    if (t < 256) g_stats[t] = 0.f;
    if (t == 0) { g_prefix = 0; g_krem = K_IDX; }
}

// histogram pass over positive-float keys (uint order == float order)
__global__ void k_hist(int pass) {
    __shared__ unsigned sb[2048];
    int t = threadIdx.x;
    for (int i = t; i < 2048; i += 256) sb[i] = 0;
    __syncthreads();
    unsigned pref = g_prefix;
    for (int i = blockIdx.x * 256 + t; i < NSEP; i += gridDim.x * 256) {
        unsigned key = __float_as_uint(g_sep[i]);
        if (pass == 0) {
            atomicAdd(&sb[key >> 21], 1u);
        } else if (pass == 1) {
            if ((key >> 21) == pref) atomicAdd(&sb[(key >> 10) & 2047u], 1u);
        } else {
            if ((key >> 10) == pref) atomicAdd(&sb[key & 1023u], 1u);
        }
    }
    __syncthreads();
    for (int i = t; i < 2048; i += 256) if (sb[i]) atomicAdd(&g_bins[i], sb[i]);
}

__global__ void k_scan(int pass) {
    if (threadIdx.x == 0) {
        unsigned k = g_krem, cum = 0;
        int sel = 0;
        int nb = (pass == 2) ? 1024 : 2048;
        for (int i = 0; i < nb; ++i) {
            unsigned cc = g_bins[i];
            if (cum + cc > k) { sel = i; break; }
            cum += cc;
        }
        g_krem = k - cum;
        unsigned p = (g_prefix << ((pass == 2) ? 10 : 11)) | (unsigned)sel;
        g_prefix = p;
        if (pass == 2) g_thr = __uint_as_float(p);
    }
    __syncthreads();
    for (int i = threadIdx.x; i < 2048; i += blockDim.x) g_bins[i] = 0;
}

// ---------------- direct 3x3 conv (fp32), persistent, fused pre/post -------
// STAGE 1: in = x, epilogue: *gate, bn1 stats, out = g_y1
// STAGE 2: in = relu(bn1(g_y1)) (fused at load), bn2 stats, out = g_y2
// SMEM: ws[36864] weights (i,k,o layout), xs[15360] padded tiles / out staging,
//       bnsum[64], bnsq[64], gsm[128]
template <int STAGE>
__global__ __launch_bounds__(256, 1)
void k_conv(const float* __restrict__ xin, const float* __restrict__ wq) {
    extern __shared__ float sm[];
    float* ws    = sm;              // 36864 floats
    float* xs    = ws + 36864;      // 15360 floats (2 imgs * 64ch * 120)
    float* bnsum = xs + 15360;      // 64
    float* bnsq  = bnsum + 64;      // 64
    float* gsm   = bnsq + 64;       // 128

    int t = threadIdx.x;

    // weights: global [o][i][ky][kx] -> smem [(i*9+k)*64 + o]
    for (int idx = t; idx < 36864; idx += 256) {
        int o = idx / 576, r = idx - o * 576;
        ws[r * 64 + o] = wq[idx];
    }
    if (t < 64) { bnsum[t] = 0.f; bnsq[t] = 0.f; }
    __syncthreads();

    int img = t >> 7;        // 0..1
    int rr  = t & 127;
    int oy  = rr >> 4;       // 0..7
    int og  = rr & 15;       // 0..15
    int o0  = og * 4;

    float thr = (STAGE == 1) ? g_thr : 0.f;
    const float4* wv4 = (const float4*)ws;
    float* yout = (STAGE == 1) ? g_y1 : g_y2;
    const float* src_base = (STAGE == 1) ? xin : (const float*)g_y1;

    for (int pair = blockIdx.x; pair < B / 2; pair += gridDim.x) {
        size_t base = (size_t)pair * 2 * NPIX;

        // zero padded tiles
        for (int i = t; i < 15360; i += 256) xs[i] = 0.f;
        if (STAGE == 1 && t < 128) {
            int ii = t >> 6, cc = t & 63;
            gsm[t] = fmaxf(g_sep[(pair * 2 + ii) * 64 + cc] - thr, 0.f);
        }
        __syncthreads();

        // load interior (+ fused relu(bn1) for STAGE 2)
        const float4* src = (const float4*)(src_base + base);
        for (int v = t; v < 2048; v += 256) {
            float4 d = src[v];
            int im  = v >> 10;
            int rem = v & 1023;
            int c   = rem >> 4;
            int q   = rem & 15;
            int y   = q >> 1;
            int x0  = (q & 1) * 4;
            float vv[4] = {d.x, d.y, d.z, d.w};
            float* dst = xs + im * 7680 + c * 120 + (y + 1) * 12 + x0 + 1;
            if (STAGE == 2) {
                float s1 = g_bnp[c], h1 = g_bnp[64 + c];
#pragma unroll
                for (int e = 0; e < 4; ++e) dst[e] = fmaxf(fmaf(vv[e], s1, h1), 0.f);
            } else {
#pragma unroll
                for (int e = 0; e < 4; ++e) dst[e] = vv[e];
            }
        }
        __syncthreads();

        // compute: 4 out-channels x 8 out-x for row oy
        float a[4][8];
#pragma unroll
        for (int j = 0; j < 4; ++j)
#pragma unroll
            for (int ox = 0; ox < 8; ++ox) a[j][ox] = 0.f;

        const float* xc = xs + img * 7680 + oy * 12;
#pragma unroll 2
        for (int i = 0; i < 64; ++i) {
            const float* xci = xc + i * 120;
#pragma unroll
            for (int ky = 0; ky < 3; ++ky) {
                const float* xr = xci + ky * 12;
                float4 p0 = *(const float4*)(xr);
                float4 p1 = *(const float4*)(xr + 4);
                float4 p2 = *(const float4*)(xr + 8);
                float xv[10] = {p0.x, p0.y, p0.z, p0.w,
                                p1.x, p1.y, p1.z, p1.w,
                                p2.x, p2.y};
#pragma unroll
                for (int kx = 0; kx < 3; ++kx) {
                    float4 w = wv4[(i * 9 + ky * 3 + kx) * 16 + og];
#pragma unroll
                    for (int ox = 0; ox < 8; ++ox) {
                        float xvv = xv[ox + kx];
                        a[0][ox] = fmaf(w.x, xvv, a[0][ox]);
                        a[1][ox] = fmaf(w.y, xvv, a[1][ox]);
                        a[2][ox] = fmaf(w.z, xvv, a[2][ox]);
                        a[3][ox] = fmaf(w.w, xvv, a[3][ox]);
                    }
                }
            }
        }
        __syncthreads();   // all xs reads done before reuse as out staging

        // epilogue: gate (STAGE1), bn stats, stage to smem (padded stride 65)
        float* os = xs;
#pragma unroll
        for (int j = 0; j < 4; ++j) {
            float g = (STAGE == 1) ? gsm[img * 64 + o0 + j] : 1.f;
            float ls = 0.f, lq = 0.f;
#pragma unroll
            for (int ox = 0; ox < 8; ++ox) {
                float v = a[j][ox] * g;
                ls += v;
                lq += v * v;
                os[img * 4160 + (o0 + j) * 65 + oy * 8 + ox] = v;
            }
            atomicAdd(&bnsum[o0 + j], ls);
            atomicAdd(&bnsq[o0 + j], lq);
        }
        __syncthreads();

        // coalesced global writeback
        for (int e = t; e < 8192; e += 256) {
            int im = e >> 12, r2 = e & 4095;
            int o = r2 >> 6, p = r2 & 63;
            yout[base + e] = os[im * 4160 + o * 65 + p];
        }
        __syncthreads();
    }

    // flush bn partial stats
    if (t < 64) {
        int off = (STAGE == 1) ? 0 : 128;
        atomicAdd(&g_stats[off + t], bnsum[t]);
        atomicAdd(&g_stats[off + 64 + t], bnsq[t]);
    }
}

// ---------------- BN finalize ----------------------------------------------
__global__ void k_bnfin(int stage, const float* __restrict__ gamma,
                        const float* __restrict__ beta) {
    int c = threadIdx.x;
    if (c >= 64) return;
    int off = (stage == 1) ? 0 : 128;
    float n = (float)NSEP;
    float mean = g_stats[off + c] / n;
    float var  = g_stats[off + 64 + c] / n - mean * mean;
    float inv  = rsqrtf(var + 1e-5f);
    float s    = gamma[c] * inv;
    g_bnp[off + c]      = s;
    g_bnp[off + 64 + c] = beta[c] - mean * s;
}

// ---------------- final: relu(bn2(y2) + x) ----------------------------------
__global__ void k_final(const float* __restrict__ x, float* __restrict__ out) {
    const float4* xv = (const float4*)x;
    const float4* yv = (const float4*)g_y2;
    float4* ov = (float4*)out;
    int total = (B * NPIX) / 4;
    for (int i = blockIdx.x * blockDim.x + threadIdx.x; i < total;
         i += gridDim.x * blockDim.x) {
        int c = (i >> 4) & 63;
        float s = g_bnp[128 + c], h = g_bnp[192 + c];
        float4 v = yv[i], r = xv[i], o;
        o.x = fmaxf(fmaf(v.x, s, h) + r.x, 0.f);
        o.y = fmaxf(fmaf(v.y, s, h) + r.y, 0.f);
        o.z = fmaxf(fmaf(v.z, s, h) + r.z, 0.f);
        o.w = fmaxf(fmaf(v.w, s, h) + r.w, 0.f);
        ov[i] = o;
    }
}

// ---------------- launch ----------------------------------------------------
extern "C" void kernel_launch(void* const* d_in, const int* in_sizes, int n_in,
                              void* d_out, int out_size) {
    const float* x   = (const float*)d_in[0];
    const float* c1w = (const float*)d_in[1];
    const float* c2w = (const float*)d_in[2];
    const float* f1w = (const float*)d_in[3];
    const float* f1b = (const float*)d_in[4];
    const float* f2w = (const float*)d_in[5];
    const float* f2b = (const float*)d_in[6];
    const float* g1  = (const float*)d_in[7];
    const float* b1  = (const float*)d_in[8];
    const float* g2  = (const float*)d_in[9];
    const float* b2  = (const float*)d_in[10];
    float* out = (float*)d_out;

    const int SMEM_BYTES = (36864 + 15360 + 64 + 64 + 128) * 4;  // 209920
    cudaFuncSetAttribute(k_conv<1>, cudaFuncAttributeMaxDynamicSharedMemorySize, SMEM_BYTES);
    cudaFuncSetAttribute(k_conv<2>, cudaFuncAttributeMaxDynamicSharedMemorySize, SMEM_BYTES);

    // 1) SE gate values
    k_gate<<<B / 4, 256>>>(x, f1w, f1b, f2w, f2b);

    // 2) exact 20%-quantile threshold via 3-pass radix select
    k_init<<<1, 256>>>();
    for (int p = 0; p < 3; ++p) {
        k_hist<<<256, 256>>>(p);
        k_scan<<<1, 256>>>(p);
    }

    // 3) conv1 * gate, bn1 stats
    k_conv<1><<<NSM, 256, SMEM_BYTES>>>(x, c1w);
    k_bnfin<<<1, 64>>>(1, g1, b1);

    // 4) conv2(relu(bn1(.))), bn2 stats
    k_conv<2><<<NSM, 256, SMEM_BYTES>>>(x, c2w);
    k_bnfin<<<1, 64>>>(2, g2, b2);

    // 5) relu(bn2 + residual)
    k_final<<<2048, 256>>>(x, out);
}